// round 1
// baseline (speedup 1.0000x reference)
#include <cuda_runtime.h>
#include <cuda_bf16.h>
#include <cstdint>

// ---------------------------------------------------------------------------
// Problem constants
// ---------------------------------------------------------------------------
#define NPF 20000
#define NGW 100000
#define NSW 30000
#define D   128

// ---------------------------------------------------------------------------
// Device scratch (no allocations allowed -> __device__ globals)
// ---------------------------------------------------------------------------
__device__ float g_sum_gw[(size_t)NGW * D];  // pfas -> gw aggregation
__device__ float g_sum_sw[(size_t)NSW * D];  // pfas -> sw aggregation
__device__ float g_sum_gp[(size_t)NPF * D];  // gw   -> pfas aggregation
__device__ float g_sum_sp[(size_t)NPF * D];  // sw   -> pfas aggregation
__device__ float g_cnt_gw[NGW];              // counts, converted to 1/max(c,1)
__device__ float g_cnt_sw[NSW];
__device__ float g_cnt_gp[NPF];
__device__ float g_cnt_sp[NPF];

// ---------------------------------------------------------------------------
// Zero scratch (float4 stores)
// ---------------------------------------------------------------------------
__global__ void zero_kernel(float* __restrict__ p, int n4) {
    int i = blockIdx.x * blockDim.x + threadIdx.x;
    if (i < n4) reinterpret_cast<float4*>(p)[i] = make_float4(0.f, 0.f, 0.f, 0.f);
}

// ---------------------------------------------------------------------------
// Edge scatter: one warp per edge. Each lane reads 16B of the source feature
// row and issues a single red.global.add.v4.f32 into the destination
// accumulator. Lane 0 bumps the count.
// ---------------------------------------------------------------------------
__global__ __launch_bounds__(256) void scatter_kernel(
    const float* __restrict__ x_src,
    const int*   __restrict__ src,
    const int*   __restrict__ dst,
    float* __restrict__ sum,
    float* __restrict__ cnt,
    int E)
{
    int warp = (blockIdx.x * blockDim.x + threadIdx.x) >> 5;
    int lane = threadIdx.x & 31;
    if (warp >= E) return;

    int s = __ldg(&src[warp]);
    int d = __ldg(&dst[warp]);

    const float4 v = *reinterpret_cast<const float4*>(x_src + (size_t)s * D + lane * 4);
    float* p = sum + (size_t)d * D + lane * 4;
    asm volatile("red.global.add.v4.f32 [%0], {%1,%2,%3,%4};"
                 :: "l"(p), "f"(v.x), "f"(v.y), "f"(v.z), "f"(v.w) : "memory");
    if (lane == 0) atomicAdd(&cnt[d], 1.0f);
}

// ---------------------------------------------------------------------------
// cnt -> 1/max(cnt, 1) in place
// ---------------------------------------------------------------------------
__global__ void inv_kernel(float* __restrict__ c, int n) {
    int i = blockIdx.x * blockDim.x + threadIdx.x;
    if (i < n) c[i] = 1.0f / fmaxf(c[i], 1.0f);
}

// ---------------------------------------------------------------------------
// Fused GEMM:
//   h[row, :] = sum_seg  A_seg[row, :] * (S_seg ? S_seg[row] : 1)  @ W_seg
//   h += bias1 (+ bias2)
//   MODE 0: out[row*128 + c] = relu(h)                 (pfas full features)
//   MODE 1: out[row] = relu(h) . whead + bhead          (gw / sw heads)
//
// 128 rows x 128 cols per block, 256 threads, 8x8 register tile, KC=16.
// ---------------------------------------------------------------------------
template<int NSEG, int MODE>
__global__ __launch_bounds__(256) void gemm_fused(
    const float* __restrict__ A0, const float* __restrict__ A1,
    const float* __restrict__ A2, const float* __restrict__ A3,
    const float* __restrict__ S0, const float* __restrict__ S1,
    const float* __restrict__ S2, const float* __restrict__ S3,
    const float* __restrict__ W0, const float* __restrict__ W1,
    const float* __restrict__ W2, const float* __restrict__ W3,
    const float* __restrict__ bias1, const float* __restrict__ bias2,
    const float* __restrict__ whead, const float* __restrict__ bhead,
    float* __restrict__ out, int n_rows)
{
    constexpr int KC  = 16;
    constexpr int LDT = 132;   // padded stride (16B aligned, breaks conflicts)
    __shared__ float As[KC][LDT];   // As[kk][row]
    __shared__ float Ws[KC][LDT];   // Ws[kk][col]
    __shared__ float red[128];

    const int t    = threadIdx.x;
    const int row0 = blockIdx.x * 128;
    const int trow = t >> 4;        // 0..15
    const int tcol = t & 15;        // 0..15

    const float* Aseg[4] = {A0, A1, A2, A3};
    const float* Sseg[4] = {S0, S1, S2, S3};
    const float* Wseg[4] = {W0, W1, W2, W3};

    float acc[8][8];
#pragma unroll
    for (int i = 0; i < 8; i++)
#pragma unroll
        for (int j = 0; j < 8; j++) acc[i][j] = 0.f;

    const int nchunks = NSEG * D / KC;
    for (int ch = 0; ch < nchunks; ch++) {
        const int k0   = ch * KC;
        const int seg  = k0 / D;
        const int kin0 = k0 % D;
        const float* A = Aseg[seg];
        const float* S = Sseg[seg];
        const float* W = Wseg[seg];

        // --- A tile: 128 rows x KC, transposed into As[kk][row], row-scaled
#pragma unroll
        for (int it = 0; it < 2; it++) {
            int idx  = t + it * 256;     // 0..511
            int row  = idx >> 2;         // 0..127
            int q    = idx & 3;          // 0..3 (quad of 4 k-values)
            int grow = row0 + row;
            float4 v = make_float4(0.f, 0.f, 0.f, 0.f);
            if (grow < n_rows) {
                v = *reinterpret_cast<const float4*>(A + (size_t)grow * D + kin0 + q * 4);
                if (S) {
                    float sc = S[grow];
                    v.x *= sc; v.y *= sc; v.z *= sc; v.w *= sc;
                }
            }
            As[q * 4 + 0][row] = v.x;
            As[q * 4 + 1][row] = v.y;
            As[q * 4 + 2][row] = v.z;
            As[q * 4 + 3][row] = v.w;
        }
        // --- W tile: KC x 128
#pragma unroll
        for (int it = 0; it < 2; it++) {
            int idx = t + it * 256;      // 0..511
            int kk  = idx >> 5;          // 0..15
            int cq  = idx & 31;          // 0..31
            float4 w = *reinterpret_cast<const float4*>(W + (size_t)(kin0 + kk) * D + cq * 4);
            *reinterpret_cast<float4*>(&Ws[kk][cq * 4]) = w;
        }
        __syncthreads();

#pragma unroll
        for (int kk = 0; kk < KC; kk++) {
            float4 a0 = *reinterpret_cast<const float4*>(&As[kk][trow * 4]);
            float4 a1 = *reinterpret_cast<const float4*>(&As[kk][64 + trow * 4]);
            float4 w0 = *reinterpret_cast<const float4*>(&Ws[kk][tcol * 4]);
            float4 w1 = *reinterpret_cast<const float4*>(&Ws[kk][64 + tcol * 4]);
            float a[8] = {a0.x, a0.y, a0.z, a0.w, a1.x, a1.y, a1.z, a1.w};
            float w[8] = {w0.x, w0.y, w0.z, w0.w, w1.x, w1.y, w1.z, w1.w};
#pragma unroll
            for (int i = 0; i < 8; i++)
#pragma unroll
                for (int j = 0; j < 8; j++) acc[i][j] += a[i] * w[j];
        }
        __syncthreads();
    }

    // column / row index helpers for the 4+4 split layout
    int cidx[8], ridx[8];
#pragma unroll
    for (int j = 0; j < 8; j++)
        cidx[j] = (j < 4) ? (tcol * 4 + j) : (64 + tcol * 4 + (j - 4));
#pragma unroll
    for (int i = 0; i < 8; i++)
        ridx[i] = (i < 4) ? (trow * 4 + i) : (64 + trow * 4 + (i - 4));

    float b[8];
#pragma unroll
    for (int j = 0; j < 8; j++)
        b[j] = bias1[cidx[j]] + (bias2 ? bias2[cidx[j]] : 0.f);

    if (MODE == 0) {
#pragma unroll
        for (int i = 0; i < 8; i++) {
            int grow = row0 + ridx[i];
            if (grow < n_rows) {
#pragma unroll
                for (int j = 0; j < 8; j++)
                    out[(size_t)grow * D + cidx[j]] = fmaxf(acc[i][j] + b[j], 0.f);
            }
        }
    } else {
        float wh[8];
#pragma unroll
        for (int j = 0; j < 8; j++) wh[j] = whead[cidx[j]];
        if (t < 128) red[t] = 0.f;
        __syncthreads();
#pragma unroll
        for (int i = 0; i < 8; i++) {
            float partial = 0.f;
#pragma unroll
            for (int j = 0; j < 8; j++)
                partial += fmaxf(acc[i][j] + b[j], 0.f) * wh[j];
            atomicAdd(&red[ridx[i]], partial);
        }
        __syncthreads();
        if (t < 128) {
            int grow = row0 + t;
            if (grow < n_rows) out[grow] = red[t] + bhead[0];
        }
    }
}

// ---------------------------------------------------------------------------
// Launch
// ---------------------------------------------------------------------------
extern "C" void kernel_launch(void* const* d_in, const int* in_sizes, int n_in,
                              void* d_out, int out_size)
{
    const float* x_pfas = (const float*)d_in[0];
    const float* x_gw   = (const float*)d_in[1];
    const float* x_sw   = (const float*)d_in[2];
    const int* ei_pg_src = (const int*)d_in[3];
    const int* ei_pg_dst = (const int*)d_in[4];
    const int* ei_gp_src = (const int*)d_in[5];
    const int* ei_gp_dst = (const int*)d_in[6];
    const int* ei_ps_src = (const int*)d_in[7];
    const int* ei_ps_dst = (const int*)d_in[8];
    const int* ei_sp_src = (const int*)d_in[9];
    const int* ei_sp_dst = (const int*)d_in[10];
    const float* Wl_pg = (const float*)d_in[11];
    const float* bl_pg = (const float*)d_in[12];
    const float* Wr_pg = (const float*)d_in[13];
    const float* Wl_gp = (const float*)d_in[14];
    const float* bl_gp = (const float*)d_in[15];
    const float* Wr_gp = (const float*)d_in[16];
    const float* Wl_ps = (const float*)d_in[17];
    const float* bl_ps = (const float*)d_in[18];
    const float* Wr_ps = (const float*)d_in[19];
    const float* Wl_sp = (const float*)d_in[20];
    const float* bl_sp = (const float*)d_in[21];
    const float* Wr_sp = (const float*)d_in[22];
    const float* W_gw  = (const float*)d_in[23];
    const float* b_gw  = (const float*)d_in[24];
    const float* W_sw  = (const float*)d_in[25];
    const float* b_sw  = (const float*)d_in[26];

    const int E_PG = in_sizes[3];
    const int E_GP = in_sizes[5];
    const int E_PS = in_sizes[7];
    const int E_SP = in_sizes[9];

    float* out = (float*)d_out;
    float* out_hpf = out;                       // [20000, 128]
    float* out_gw  = out + (size_t)NPF * D;     // [100000]
    float* out_sw  = out_gw + NGW;              // [30000]

    // scratch symbol addresses (device-side pointers usable from host launch args
    // via cudaGetSymbolAddress; host API call, no allocation, capture-safe)
    static float *sum_gw = nullptr, *sum_sw = nullptr, *sum_gp = nullptr, *sum_sp = nullptr;
    static float *cnt_gw = nullptr, *cnt_sw = nullptr, *cnt_gp = nullptr, *cnt_sp = nullptr;
    if (!sum_gw) {
        cudaGetSymbolAddress((void**)&sum_gw, g_sum_gw);
        cudaGetSymbolAddress((void**)&sum_sw, g_sum_sw);
        cudaGetSymbolAddress((void**)&sum_gp, g_sum_gp);
        cudaGetSymbolAddress((void**)&sum_sp, g_sum_sp);
        cudaGetSymbolAddress((void**)&cnt_gw, g_cnt_gw);
        cudaGetSymbolAddress((void**)&cnt_sw, g_cnt_sw);
        cudaGetSymbolAddress((void**)&cnt_gp, g_cnt_gp);
        cudaGetSymbolAddress((void**)&cnt_sp, g_cnt_sp);
    }

    // ---- 1) zero accumulators ----
    auto zero = [](float* p, size_t n) {
        int n4 = (int)(n / 4);
        zero_kernel<<<(n4 + 255) / 256, 256>>>(p, n4);
    };
    zero(sum_gw, (size_t)NGW * D);
    zero(sum_sw, (size_t)NSW * D);
    zero(sum_gp, (size_t)NPF * D);
    zero(sum_sp, (size_t)NPF * D);
    zero(cnt_gw, NGW);
    zero(cnt_sw, NSW);
    zero(cnt_gp, NPF);
    zero(cnt_sp, NPF);

    // ---- 2) edge scatter (warp per edge) ----
    auto scatter = [](const float* x, const int* s, const int* d,
                      float* sum, float* cnt, int E) {
        int blocks = (E + 7) / 8;   // 8 warps / block
        scatter_kernel<<<blocks, 256>>>(x, s, d, sum, cnt, E);
    };
    scatter(x_pfas, ei_pg_src, ei_pg_dst, sum_gw, cnt_gw, E_PG);
    scatter(x_gw,   ei_gp_src, ei_gp_dst, sum_gp, cnt_gp, E_GP);
    scatter(x_pfas, ei_ps_src, ei_ps_dst, sum_sw, cnt_sw, E_PS);
    scatter(x_sw,   ei_sp_src, ei_sp_dst, sum_sp, cnt_sp, E_SP);

    // ---- 3) counts -> reciprocals ----
    inv_kernel<<<(NGW + 255) / 256, 256>>>(cnt_gw, NGW);
    inv_kernel<<<(NSW + 255) / 256, 256>>>(cnt_sw, NSW);
    inv_kernel<<<(NPF + 255) / 256, 256>>>(cnt_gp, NPF);
    inv_kernel<<<(NPF + 255) / 256, 256>>>(cnt_sp, NPF);

    // ---- 4) fused GEMMs ----
    // pfas: h_pf = relu(mean_gp@Wl_gp + x@Wr_gp + mean_sp@Wl_sp + x@Wr_sp + bl_gp + bl_sp)
    gemm_fused<4, 0><<<(NPF + 127) / 128, 256>>>(
        sum_gp, x_pfas, sum_sp, x_pfas,
        cnt_gp, nullptr, cnt_sp, nullptr,
        Wl_gp, Wr_gp, Wl_sp, Wr_sp,
        bl_gp, bl_sp, nullptr, nullptr,
        out_hpf, NPF);

    // gw head: out_gw = relu(mean_gw@Wl_pg + x_gw@Wr_pg + bl_pg) @ W_gw + b_gw
    gemm_fused<2, 1><<<(NGW + 127) / 128, 256>>>(
        sum_gw, x_gw, nullptr, nullptr,
        cnt_gw, nullptr, nullptr, nullptr,
        Wl_pg, Wr_pg, nullptr, nullptr,
        bl_pg, nullptr, W_gw, b_gw,
        out_gw, NGW);

    // sw head: out_sw = relu(mean_sw@Wl_ps + x_sw@Wr_ps + bl_ps) @ W_sw + b_sw
    gemm_fused<2, 1><<<(NSW + 127) / 128, 256>>>(
        sum_sw, x_sw, nullptr, nullptr,
        cnt_sw, nullptr, nullptr, nullptr,
        Wl_ps, Wr_ps, nullptr, nullptr,
        bl_ps, nullptr, W_sw, b_sw,
        out_sw, NSW);

    (void)n_in; (void)out_size; (void)in_sizes;
}

// round 2
// speedup vs baseline: 1.3324x; 1.3324x over previous
#include <cuda_runtime.h>
#include <cuda_bf16.h>
#include <cstdint>

// ---------------------------------------------------------------------------
// Problem constants
// ---------------------------------------------------------------------------
#define NPF 20000
#define NGW 100000
#define NSW 30000
#define D   128

#define EPG 1600000
#define EGP 640000
#define EPS 480000
#define ESP 320000
#define ETOT (EPG + EGP + EPS + ESP)

// destination-space layout inside the shared counter arrays:
//   rel0 pg -> NGW  at off 0
//   rel1 gp -> NPF  at off NGW
//   rel2 ps -> NSW  at off NGW+NPF
//   rel3 sp -> NPF  at off NGW+NPF+NSW
#define NTOT (NGW + NPF + NSW + NPF)

// ---------------------------------------------------------------------------
// Device scratch (no allocations allowed -> __device__ globals)
// ---------------------------------------------------------------------------
__device__ float g_mean_gw[(size_t)NGW * D];
__device__ float g_mean_sw[(size_t)NSW * D];
__device__ float g_mean_gp[(size_t)NPF * D];
__device__ float g_mean_sp[(size_t)NPF * D];
__device__ int   g_cnt[NTOT];
__device__ int   g_rowptr[NTOT];
__device__ int   g_cursor[NTOT];
__device__ int   g_perm[ETOT];
__device__ int   g_partials[4 * 128];
__device__ float g_wr_comb[D * D];

// ---------------------------------------------------------------------------
// small utility kernels
// ---------------------------------------------------------------------------
__global__ void zero_int_kernel(int* __restrict__ p, int n4) {
    int i = blockIdx.x * blockDim.x + threadIdx.x;
    if (i < n4) reinterpret_cast<int4*>(p)[i] = make_int4(0, 0, 0, 0);
}

__global__ void addw_kernel(const float* __restrict__ a, const float* __restrict__ b,
                            float* __restrict__ o) {
    int i = blockIdx.x * blockDim.x + threadIdx.x;
    if (i < D * D) o[i] = a[i] + b[i];
}

// ---------------------------------------------------------------------------
// CSR build: histogram -> 3-kernel scan -> permutation
// ---------------------------------------------------------------------------
__global__ void hist_kernel(const int* __restrict__ dst, int* __restrict__ cnt, int E) {
    int e = blockIdx.x * blockDim.x + threadIdx.x;
    if (e < E) atomicAdd(&cnt[dst[e]], 1);
}

// 1024 elements per block, 256 threads (4 elements each, contiguous per thread)
__global__ void scan_reduce_kernel(const int* __restrict__ cnt, int n,
                                   int* __restrict__ partials) {
    __shared__ int s[256];
    int t = threadIdx.x;
    int base = blockIdx.x * 1024 + t * 4;
    int sum = 0;
#pragma unroll
    for (int j = 0; j < 4; j++) {
        int idx = base + j;
        if (idx < n) sum += cnt[idx];
    }
    s[t] = sum;
    __syncthreads();
    for (int off = 128; off > 0; off >>= 1) {
        if (t < off) s[t] += s[t + off];
        __syncthreads();
    }
    if (t == 0) partials[blockIdx.x] = s[0];
}

__global__ void scan_partials_kernel(int* __restrict__ partials, int nb) {
    int run = 0;
    for (int i = 0; i < nb; i++) {
        int v = partials[i];
        partials[i] = run;
        run += v;
    }
}

__global__ void scan_write_kernel(const int* __restrict__ cnt, int n,
                                  const int* __restrict__ partials,
                                  int* __restrict__ rowptr,
                                  int* __restrict__ cursor) {
    __shared__ int wsum[8];
    __shared__ int woff[8];
    int t = threadIdx.x;
    int lane = t & 31, warp = t >> 5;
    int base = blockIdx.x * 1024 + t * 4;
    int v[4];
    int tsum = 0;
#pragma unroll
    for (int j = 0; j < 4; j++) {
        int idx = base + j;
        v[j] = (idx < n) ? cnt[idx] : 0;
        tsum += v[j];
    }
    // warp inclusive scan of per-thread sums
    int incl = tsum;
#pragma unroll
    for (int o = 1; o < 32; o <<= 1) {
        int y = __shfl_up_sync(0xffffffffu, incl, o);
        if (lane >= o) incl += y;
    }
    int excl = incl - tsum;
    if (lane == 31) wsum[warp] = incl;
    __syncthreads();
    if (t == 0) {
        int r = 0;
        for (int i = 0; i < 8; i++) { woff[i] = r; r += wsum[i]; }
    }
    __syncthreads();
    int run = partials[blockIdx.x] + woff[warp] + excl;
#pragma unroll
    for (int j = 0; j < 4; j++) {
        int idx = base + j;
        if (idx < n) { rowptr[idx] = run; cursor[idx] = run; run += v[j]; }
    }
}

__global__ void permute_kernel(const int* __restrict__ src, const int* __restrict__ dst,
                               int* __restrict__ cursor, int* __restrict__ perm, int E) {
    int e = blockIdx.x * blockDim.x + threadIdx.x;
    if (e < E) {
        int pos = atomicAdd(&cursor[dst[e]], 1);
        perm[pos] = src[e];
    }
}

// ---------------------------------------------------------------------------
// Pull aggregation: one warp per destination node. Accumulates mean of
// neighbor rows directly (no atomics, no zero-init of the 77MB accumulators).
// ---------------------------------------------------------------------------
__global__ __launch_bounds__(256) void aggregate_kernel(
    const float* __restrict__ x,
    const int*   __restrict__ rowptr,
    const int*   __restrict__ perm,
    float* __restrict__ outmean,
    int N, int E)
{
    int w = (blockIdx.x * blockDim.x + threadIdx.x) >> 5;
    int lane = threadIdx.x & 31;
    if (w >= N) return;

    int start = rowptr[w];
    int end   = (w + 1 < N) ? rowptr[w + 1] : E;

    float4 acc = make_float4(0.f, 0.f, 0.f, 0.f);
    for (int e0 = start; e0 < end; e0 += 32) {
        int idx = (e0 + lane < end) ? perm[e0 + lane] : 0;
        int m = min(32, end - e0);
        for (int j = 0; j < m; j++) {
            int s = __shfl_sync(0xffffffffu, idx, j);
            const float4 v = *reinterpret_cast<const float4*>(x + (size_t)s * D + lane * 4);
            acc.x += v.x; acc.y += v.y; acc.z += v.z; acc.w += v.w;
        }
    }
    float inv = 1.0f / fmaxf((float)(end - start), 1.0f);
    acc.x *= inv; acc.y *= inv; acc.z *= inv; acc.w *= inv;
    *reinterpret_cast<float4*>(outmean + (size_t)w * D + lane * 4) = acc;
}

// ---------------------------------------------------------------------------
// Fused GEMM (A rows already mean-scaled):
//   h[row, :] = sum_seg A_seg[row, :] @ W_seg  + bias1 (+ bias2)
//   MODE 0: out[row*128 + c] = relu(h)                 (pfas full features)
//   MODE 1: out[row] = relu(h) . whead + bhead         (gw / sw heads)
// 128x128 tile per block, 256 threads, 8x8 register tile, KC=16.
// ---------------------------------------------------------------------------
template<int NSEG, int MODE>
__global__ __launch_bounds__(256) void gemm_fused(
    const float* __restrict__ A0, const float* __restrict__ A1,
    const float* __restrict__ A2, const float* __restrict__ A3,
    const float* __restrict__ W0, const float* __restrict__ W1,
    const float* __restrict__ W2, const float* __restrict__ W3,
    const float* __restrict__ bias1, const float* __restrict__ bias2,
    const float* __restrict__ whead, const float* __restrict__ bhead,
    float* __restrict__ out, int n_rows)
{
    constexpr int KC  = 16;
    constexpr int LDT = 132;
    __shared__ float As[KC][LDT];   // As[kk][row]
    __shared__ float Ws[KC][LDT];   // Ws[kk][col]
    __shared__ float red[128];

    const int t    = threadIdx.x;
    const int row0 = blockIdx.x * 128;
    const int trow = t >> 4;
    const int tcol = t & 15;

    const float* Aseg[4] = {A0, A1, A2, A3};
    const float* Wseg[4] = {W0, W1, W2, W3};

    float acc[8][8];
#pragma unroll
    for (int i = 0; i < 8; i++)
#pragma unroll
        for (int j = 0; j < 8; j++) acc[i][j] = 0.f;

    const int nchunks = NSEG * D / KC;
    for (int ch = 0; ch < nchunks; ch++) {
        const int k0   = ch * KC;
        const int seg  = k0 / D;
        const int kin0 = k0 % D;
        const float* A = Aseg[seg];
        const float* W = Wseg[seg];

#pragma unroll
        for (int it = 0; it < 2; it++) {
            int idx  = t + it * 256;
            int row  = idx >> 2;
            int q    = idx & 3;
            int grow = row0 + row;
            float4 v = make_float4(0.f, 0.f, 0.f, 0.f);
            if (grow < n_rows)
                v = *reinterpret_cast<const float4*>(A + (size_t)grow * D + kin0 + q * 4);
            As[q * 4 + 0][row] = v.x;
            As[q * 4 + 1][row] = v.y;
            As[q * 4 + 2][row] = v.z;
            As[q * 4 + 3][row] = v.w;
        }
#pragma unroll
        for (int it = 0; it < 2; it++) {
            int idx = t + it * 256;
            int kk  = idx >> 5;
            int cq  = idx & 31;
            float4 w = *reinterpret_cast<const float4*>(W + (size_t)(kin0 + kk) * D + cq * 4);
            *reinterpret_cast<float4*>(&Ws[kk][cq * 4]) = w;
        }
        __syncthreads();

#pragma unroll
        for (int kk = 0; kk < KC; kk++) {
            float4 a0 = *reinterpret_cast<const float4*>(&As[kk][trow * 4]);
            float4 a1 = *reinterpret_cast<const float4*>(&As[kk][64 + trow * 4]);
            float4 w0 = *reinterpret_cast<const float4*>(&Ws[kk][tcol * 4]);
            float4 w1 = *reinterpret_cast<const float4*>(&Ws[kk][64 + tcol * 4]);
            float a[8] = {a0.x, a0.y, a0.z, a0.w, a1.x, a1.y, a1.z, a1.w};
            float w[8] = {w0.x, w0.y, w0.z, w0.w, w1.x, w1.y, w1.z, w1.w};
#pragma unroll
            for (int i = 0; i < 8; i++)
#pragma unroll
                for (int j = 0; j < 8; j++) acc[i][j] += a[i] * w[j];
        }
        __syncthreads();
    }

    int cidx[8], ridx[8];
#pragma unroll
    for (int j = 0; j < 8; j++)
        cidx[j] = (j < 4) ? (tcol * 4 + j) : (64 + tcol * 4 + (j - 4));
#pragma unroll
    for (int i = 0; i < 8; i++)
        ridx[i] = (i < 4) ? (trow * 4 + i) : (64 + trow * 4 + (i - 4));

    float b[8];
#pragma unroll
    for (int j = 0; j < 8; j++)
        b[j] = bias1[cidx[j]] + (bias2 ? bias2[cidx[j]] : 0.f);

    if (MODE == 0) {
#pragma unroll
        for (int i = 0; i < 8; i++) {
            int grow = row0 + ridx[i];
            if (grow < n_rows) {
#pragma unroll
                for (int j = 0; j < 8; j++)
                    out[(size_t)grow * D + cidx[j]] = fmaxf(acc[i][j] + b[j], 0.f);
            }
        }
    } else {
        float wh[8];
#pragma unroll
        for (int j = 0; j < 8; j++) wh[j] = whead[cidx[j]];
        if (t < 128) red[t] = 0.f;
        __syncthreads();
#pragma unroll
        for (int i = 0; i < 8; i++) {
            float partial = 0.f;
#pragma unroll
            for (int j = 0; j < 8; j++)
                partial += fmaxf(acc[i][j] + b[j], 0.f) * wh[j];
            atomicAdd(&red[ridx[i]], partial);
        }
        __syncthreads();
        if (t < 128) {
            int grow = row0 + t;
            if (grow < n_rows) out[grow] = red[t] + bhead[0];
        }
    }
}

// ---------------------------------------------------------------------------
// Launch
// ---------------------------------------------------------------------------
extern "C" void kernel_launch(void* const* d_in, const int* in_sizes, int n_in,
                              void* d_out, int out_size)
{
    const float* x_pfas = (const float*)d_in[0];
    const float* x_gw   = (const float*)d_in[1];
    const float* x_sw   = (const float*)d_in[2];
    const int* ei_pg_src = (const int*)d_in[3];
    const int* ei_pg_dst = (const int*)d_in[4];
    const int* ei_gp_src = (const int*)d_in[5];
    const int* ei_gp_dst = (const int*)d_in[6];
    const int* ei_ps_src = (const int*)d_in[7];
    const int* ei_ps_dst = (const int*)d_in[8];
    const int* ei_sp_src = (const int*)d_in[9];
    const int* ei_sp_dst = (const int*)d_in[10];
    const float* Wl_pg = (const float*)d_in[11];
    const float* bl_pg = (const float*)d_in[12];
    const float* Wr_pg = (const float*)d_in[13];
    const float* Wl_gp = (const float*)d_in[14];
    const float* bl_gp = (const float*)d_in[15];
    const float* Wr_gp = (const float*)d_in[16];
    const float* Wl_ps = (const float*)d_in[17];
    const float* bl_ps = (const float*)d_in[18];
    const float* Wr_ps = (const float*)d_in[19];
    const float* Wl_sp = (const float*)d_in[20];
    const float* bl_sp = (const float*)d_in[21];
    const float* Wr_sp = (const float*)d_in[22];
    const float* W_gw  = (const float*)d_in[23];
    const float* b_gw  = (const float*)d_in[24];
    const float* W_sw  = (const float*)d_in[25];
    const float* b_sw  = (const float*)d_in[26];

    const int E_PG = in_sizes[3];
    const int E_GP = in_sizes[5];
    const int E_PS = in_sizes[7];
    const int E_SP = in_sizes[9];

    float* out = (float*)d_out;
    float* out_hpf = out;                       // [20000, 128]
    float* out_gw  = out + (size_t)NPF * D;     // [100000]
    float* out_sw  = out_gw + NGW;              // [30000]

    static float *mean_gw = nullptr, *mean_sw = nullptr, *mean_gp = nullptr, *mean_sp = nullptr;
    static float *wr_comb = nullptr;
    static int *cnt = nullptr, *rowptr = nullptr, *cursor = nullptr, *perm = nullptr, *partials = nullptr;
    if (!mean_gw) {
        cudaGetSymbolAddress((void**)&mean_gw, g_mean_gw);
        cudaGetSymbolAddress((void**)&mean_sw, g_mean_sw);
        cudaGetSymbolAddress((void**)&mean_gp, g_mean_gp);
        cudaGetSymbolAddress((void**)&mean_sp, g_mean_sp);
        cudaGetSymbolAddress((void**)&wr_comb, g_wr_comb);
        cudaGetSymbolAddress((void**)&cnt, g_cnt);
        cudaGetSymbolAddress((void**)&rowptr, g_rowptr);
        cudaGetSymbolAddress((void**)&cursor, g_cursor);
        cudaGetSymbolAddress((void**)&perm, g_perm);
        cudaGetSymbolAddress((void**)&partials, g_partials);
    }

    // counter-space offsets per relation
    const int off_pg = 0;
    const int off_gp = NGW;
    const int off_ps = NGW + NPF;
    const int off_sp = NGW + NPF + NSW;
    // perm-space offsets
    const int poff_pg = 0;
    const int poff_gp = E_PG;
    const int poff_ps = E_PG + E_GP;
    const int poff_sp = E_PG + E_GP + E_PS;

    // ---- 1) zero counters (small) ----
    zero_int_kernel<<<(NTOT / 4 + 255) / 256, 256>>>(cnt, NTOT / 4);

    // ---- 2) Wr_comb = Wr_gp + Wr_sp ----
    addw_kernel<<<(D * D + 255) / 256, 256>>>(Wr_gp, Wr_sp, wr_comb);

    // ---- 3) CSR build + aggregate per relation ----
    struct Rel {
        const int *src, *dst;
        const float* x;
        float* mean;
        int off, poff, N, E;
    };
    Rel rels[4] = {
        {ei_pg_src, ei_pg_dst, x_pfas, mean_gw, off_pg, poff_pg, NGW, E_PG},
        {ei_gp_src, ei_gp_dst, x_gw,   mean_gp, off_gp, poff_gp, NPF, E_GP},
        {ei_ps_src, ei_ps_dst, x_pfas, mean_sw, off_ps, poff_ps, NSW, E_PS},
        {ei_sp_src, ei_sp_dst, x_sw,   mean_sp, off_sp, poff_sp, NPF, E_SP},
    };

    for (int r = 0; r < 4; r++) {
        Rel& q = rels[r];
        hist_kernel<<<(q.E + 255) / 256, 256>>>(q.dst, cnt + q.off, q.E);
    }
    for (int r = 0; r < 4; r++) {
        Rel& q = rels[r];
        int nb = (q.N + 1023) / 1024;
        scan_reduce_kernel<<<nb, 256>>>(cnt + q.off, q.N, partials + r * 128);
        scan_partials_kernel<<<1, 1>>>(partials + r * 128, nb);
        scan_write_kernel<<<nb, 256>>>(cnt + q.off, q.N, partials + r * 128,
                                       rowptr + q.off, cursor + q.off);
    }
    for (int r = 0; r < 4; r++) {
        Rel& q = rels[r];
        permute_kernel<<<(q.E + 255) / 256, 256>>>(q.src, q.dst, cursor + q.off,
                                                   perm + q.poff, q.E);
    }
    for (int r = 0; r < 4; r++) {
        Rel& q = rels[r];
        aggregate_kernel<<<(q.N + 7) / 8, 256>>>(q.x, rowptr + q.off, perm + q.poff,
                                                 q.mean, q.N, q.E);
    }

    // ---- 4) fused GEMMs ----
    // pfas: relu(mean_gp@Wl_gp + mean_sp@Wl_sp + x_pfas@(Wr_gp+Wr_sp) + bl_gp + bl_sp)
    gemm_fused<3, 0><<<(NPF + 127) / 128, 256>>>(
        mean_gp, mean_sp, x_pfas, nullptr,
        Wl_gp, Wl_sp, wr_comb, nullptr,
        bl_gp, bl_sp, nullptr, nullptr,
        out_hpf, NPF);

    // gw head: relu(mean_gw@Wl_pg + x_gw@Wr_pg + bl_pg) @ W_gw + b_gw
    gemm_fused<2, 1><<<(NGW + 127) / 128, 256>>>(
        mean_gw, x_gw, nullptr, nullptr,
        Wl_pg, Wr_pg, nullptr, nullptr,
        bl_pg, nullptr, W_gw, b_gw,
        out_gw, NGW);

    // sw head: relu(mean_sw@Wl_ps + x_sw@Wr_ps + bl_ps) @ W_sw + b_sw
    gemm_fused<2, 1><<<(NSW + 127) / 128, 256>>>(
        mean_sw, x_sw, nullptr, nullptr,
        Wl_ps, Wr_ps, nullptr, nullptr,
        bl_ps, nullptr, W_sw, b_sw,
        out_sw, NSW);

    (void)n_in; (void)out_size;
}

// round 3
// speedup vs baseline: 1.4412x; 1.0816x over previous
#include <cuda_runtime.h>
#include <cuda_bf16.h>
#include <cstdint>

// ---------------------------------------------------------------------------
// Problem constants
// ---------------------------------------------------------------------------
#define NPF 20000
#define NGW 100000
#define NSW 30000
#define D   128

#define EPG 1600000
#define EGP 640000
#define EPS 480000
#define ESP 320000
#define ETOT (EPG + EGP + EPS + ESP)

#define NTOT (NGW + NPF + NSW + NPF)

// ---------------------------------------------------------------------------
// Device scratch (no allocations allowed -> __device__ globals)
// ---------------------------------------------------------------------------
__device__ float g_mean_gw[(size_t)NGW * D];
__device__ float g_mean_sw[(size_t)NSW * D];
__device__ float g_mean_gp[(size_t)NPF * D];
__device__ float g_mean_sp[(size_t)NPF * D];
__device__ int   g_cnt[NTOT];
__device__ int   g_rowptr[NTOT];
__device__ int   g_cursor[NTOT];
__device__ int   g_perm[ETOT];
__device__ int   g_partials[4 * 128];
__device__ float g_wr_comb[D * D];

// ---------------------------------------------------------------------------
// small utility kernels
// ---------------------------------------------------------------------------
__global__ void zero_int_kernel(int* __restrict__ p, int n4) {
    int i = blockIdx.x * blockDim.x + threadIdx.x;
    if (i < n4) reinterpret_cast<int4*>(p)[i] = make_int4(0, 0, 0, 0);
}

__global__ void addw_kernel(const float* __restrict__ a, const float* __restrict__ b,
                            float* __restrict__ o) {
    int i = blockIdx.x * blockDim.x + threadIdx.x;
    if (i < D * D) o[i] = a[i] + b[i];
}

// ---------------------------------------------------------------------------
// CSR build: histogram -> 3-kernel scan -> permutation
// ---------------------------------------------------------------------------
__global__ void hist_kernel(const int* __restrict__ dst, int* __restrict__ cnt, int E) {
    int e = blockIdx.x * blockDim.x + threadIdx.x;
    if (e < E) atomicAdd(&cnt[dst[e]], 1);
}

__global__ void scan_reduce_kernel(const int* __restrict__ cnt, int n,
                                   int* __restrict__ partials) {
    __shared__ int s[256];
    int t = threadIdx.x;
    int base = blockIdx.x * 1024 + t * 4;
    int sum = 0;
#pragma unroll
    for (int j = 0; j < 4; j++) {
        int idx = base + j;
        if (idx < n) sum += cnt[idx];
    }
    s[t] = sum;
    __syncthreads();
    for (int off = 128; off > 0; off >>= 1) {
        if (t < off) s[t] += s[t + off];
        __syncthreads();
    }
    if (t == 0) partials[blockIdx.x] = s[0];
}

__global__ void scan_partials_kernel(int* __restrict__ partials, int nb) {
    int run = 0;
    for (int i = 0; i < nb; i++) {
        int v = partials[i];
        partials[i] = run;
        run += v;
    }
}

__global__ void scan_write_kernel(const int* __restrict__ cnt, int n,
                                  const int* __restrict__ partials,
                                  int* __restrict__ rowptr,
                                  int* __restrict__ cursor) {
    __shared__ int wsum[8];
    __shared__ int woff[8];
    int t = threadIdx.x;
    int lane = t & 31, warp = t >> 5;
    int base = blockIdx.x * 1024 + t * 4;
    int v[4];
    int tsum = 0;
#pragma unroll
    for (int j = 0; j < 4; j++) {
        int idx = base + j;
        v[j] = (idx < n) ? cnt[idx] : 0;
        tsum += v[j];
    }
    int incl = tsum;
#pragma unroll
    for (int o = 1; o < 32; o <<= 1) {
        int y = __shfl_up_sync(0xffffffffu, incl, o);
        if (lane >= o) incl += y;
    }
    int excl = incl - tsum;
    if (lane == 31) wsum[warp] = incl;
    __syncthreads();
    if (t == 0) {
        int r = 0;
        for (int i = 0; i < 8; i++) { woff[i] = r; r += wsum[i]; }
    }
    __syncthreads();
    int run = partials[blockIdx.x] + woff[warp] + excl;
#pragma unroll
    for (int j = 0; j < 4; j++) {
        int idx = base + j;
        if (idx < n) { rowptr[idx] = run; cursor[idx] = run; run += v[j]; }
    }
}

__global__ void permute_kernel(const int* __restrict__ src, const int* __restrict__ dst,
                               int* __restrict__ cursor, int* __restrict__ perm, int E) {
    int e = blockIdx.x * blockDim.x + threadIdx.x;
    if (e < E) {
        int pos = atomicAdd(&cursor[dst[e]], 1);
        perm[pos] = src[e];
    }
}

// ---------------------------------------------------------------------------
// Pull aggregation: one warp per destination node.
// ---------------------------------------------------------------------------
__global__ __launch_bounds__(256) void aggregate_kernel(
    const float* __restrict__ x,
    const int*   __restrict__ rowptr,
    const int*   __restrict__ perm,
    float* __restrict__ outmean,
    int N, int E)
{
    int w = (blockIdx.x * blockDim.x + threadIdx.x) >> 5;
    int lane = threadIdx.x & 31;
    if (w >= N) return;

    int start = rowptr[w];
    int end   = (w + 1 < N) ? rowptr[w + 1] : E;

    float4 acc = make_float4(0.f, 0.f, 0.f, 0.f);
    for (int e0 = start; e0 < end; e0 += 32) {
        int idx = (e0 + lane < end) ? perm[e0 + lane] : 0;
        int m = min(32, end - e0);
        for (int j = 0; j < m; j++) {
            int s = __shfl_sync(0xffffffffu, idx, j);
            const float4 v = *reinterpret_cast<const float4*>(x + (size_t)s * D + lane * 4);
            acc.x += v.x; acc.y += v.y; acc.z += v.z; acc.w += v.w;
        }
    }
    float inv = 1.0f / fmaxf((float)(end - start), 1.0f);
    acc.x *= inv; acc.y *= inv; acc.z *= inv; acc.w *= inv;
    *reinterpret_cast<float4*>(outmean + (size_t)w * D + lane * 4) = acc;
}

// ---------------------------------------------------------------------------
// Fused GEMM with packed f32x2 FMA (FFMA2, 2 fp32 FMAs per issue slot):
//   h[row, :] = sum_seg A_seg[row, :] @ W_seg  + bias1 (+ bias2)
//   MODE 0: out[row*128 + c] = relu(h)
//   MODE 1: out[row] = relu(h) . whead + bhead
// 128x128 tile per block, 256 threads, 8x8 register tile (as 8x4 f32x2), KC=16
// ---------------------------------------------------------------------------
template<int NSEG, int MODE>
__global__ __launch_bounds__(256) void gemm_fused(
    const float* __restrict__ A0, const float* __restrict__ A1,
    const float* __restrict__ A2, const float* __restrict__ A3,
    const float* __restrict__ W0, const float* __restrict__ W1,
    const float* __restrict__ W2, const float* __restrict__ W3,
    const float* __restrict__ bias1, const float* __restrict__ bias2,
    const float* __restrict__ whead, const float* __restrict__ bhead,
    float* __restrict__ out, int n_rows)
{
    constexpr int KC  = 16;
    constexpr int LDT = 132;   // 528B row stride: 16B aligned, conflict-free
    __shared__ float As[KC][LDT];   // As[kk][row]
    __shared__ float Ws[KC][LDT];   // Ws[kk][col]
    __shared__ float red[128];

    const int t    = threadIdx.x;
    const int row0 = blockIdx.x * 128;
    const int trow = t >> 4;
    const int tcol = t & 15;

    const float* Aseg[4] = {A0, A1, A2, A3};
    const float* Wseg[4] = {W0, W1, W2, W3};

    // packed accumulators: accp[i][j2] holds output cols (2*j2, 2*j2+1) of the
    // 8-wide column group for row i
    unsigned long long accp[8][4];
#pragma unroll
    for (int i = 0; i < 8; i++)
#pragma unroll
        for (int j2 = 0; j2 < 4; j2++) accp[i][j2] = 0ull;

    const int nchunks = NSEG * D / KC;
    for (int ch = 0; ch < nchunks; ch++) {
        const int k0   = ch * KC;
        const int seg  = k0 / D;
        const int kin0 = k0 % D;
        const float* A = Aseg[seg];
        const float* W = Wseg[seg];

#pragma unroll
        for (int it = 0; it < 2; it++) {
            int idx  = t + it * 256;
            int row  = idx >> 2;
            int q    = idx & 3;
            int grow = row0 + row;
            float4 v = make_float4(0.f, 0.f, 0.f, 0.f);
            if (grow < n_rows)
                v = *reinterpret_cast<const float4*>(A + (size_t)grow * D + kin0 + q * 4);
            As[q * 4 + 0][row] = v.x;
            As[q * 4 + 1][row] = v.y;
            As[q * 4 + 2][row] = v.z;
            As[q * 4 + 3][row] = v.w;
        }
#pragma unroll
        for (int it = 0; it < 2; it++) {
            int idx = t + it * 256;
            int kk  = idx >> 5;
            int cq  = idx & 31;
            float4 w = *reinterpret_cast<const float4*>(W + (size_t)(kin0 + kk) * D + cq * 4);
            *reinterpret_cast<float4*>(&Ws[kk][cq * 4]) = w;
        }
        __syncthreads();

#pragma unroll
        for (int kk = 0; kk < KC; kk++) {
            float4 a0 = *reinterpret_cast<const float4*>(&As[kk][trow * 4]);
            float4 a1 = *reinterpret_cast<const float4*>(&As[kk][64 + trow * 4]);
            // W column pairs load directly as 64-bit (8B aligned)
            unsigned long long wp[4];
            wp[0] = *reinterpret_cast<const unsigned long long*>(&Ws[kk][tcol * 4]);
            wp[1] = *reinterpret_cast<const unsigned long long*>(&Ws[kk][tcol * 4 + 2]);
            wp[2] = *reinterpret_cast<const unsigned long long*>(&Ws[kk][64 + tcol * 4]);
            wp[3] = *reinterpret_cast<const unsigned long long*>(&Ws[kk][64 + tcol * 4 + 2]);
            float a[8] = {a0.x, a0.y, a0.z, a0.w, a1.x, a1.y, a1.z, a1.w};
#pragma unroll
            for (int i = 0; i < 8; i++) {
                unsigned long long ap;
                asm("mov.b64 %0, {%1, %1};" : "=l"(ap) : "f"(a[i]));
#pragma unroll
                for (int j2 = 0; j2 < 4; j2++)
                    asm("fma.rn.f32x2 %0, %1, %2, %0;"
                        : "+l"(accp[i][j2]) : "l"(ap), "l"(wp[j2]));
            }
        }
        __syncthreads();
    }

    // unpack to acc[8][8] with the original column mapping
    float acc[8][8];
#pragma unroll
    for (int i = 0; i < 8; i++)
#pragma unroll
        for (int j2 = 0; j2 < 4; j2++)
            asm("mov.b64 {%0, %1}, %2;"
                : "=f"(acc[i][2 * j2]), "=f"(acc[i][2 * j2 + 1]) : "l"(accp[i][j2]));

    int cidx[8], ridx[8];
#pragma unroll
    for (int j = 0; j < 8; j++)
        cidx[j] = (j < 4) ? (tcol * 4 + j) : (64 + tcol * 4 + (j - 4));
#pragma unroll
    for (int i = 0; i < 8; i++)
        ridx[i] = (i < 4) ? (trow * 4 + i) : (64 + trow * 4 + (i - 4));

    float b[8];
#pragma unroll
    for (int j = 0; j < 8; j++)
        b[j] = bias1[cidx[j]] + (bias2 ? bias2[cidx[j]] : 0.f);

    if (MODE == 0) {
#pragma unroll
        for (int i = 0; i < 8; i++) {
            int grow = row0 + ridx[i];
            if (grow < n_rows) {
#pragma unroll
                for (int j = 0; j < 8; j++)
                    out[(size_t)grow * D + cidx[j]] = fmaxf(acc[i][j] + b[j], 0.f);
            }
        }
    } else {
        float wh[8];
#pragma unroll
        for (int j = 0; j < 8; j++) wh[j] = whead[cidx[j]];
        if (t < 128) red[t] = 0.f;
        __syncthreads();
#pragma unroll
        for (int i = 0; i < 8; i++) {
            float partial = 0.f;
#pragma unroll
            for (int j = 0; j < 8; j++)
                partial += fmaxf(acc[i][j] + b[j], 0.f) * wh[j];
            atomicAdd(&red[ridx[i]], partial);
        }
        __syncthreads();
        if (t < 128) {
            int grow = row0 + t;
            if (grow < n_rows) out[grow] = red[t] + bhead[0];
        }
    }
}

// ---------------------------------------------------------------------------
// Launch
// ---------------------------------------------------------------------------
extern "C" void kernel_launch(void* const* d_in, const int* in_sizes, int n_in,
                              void* d_out, int out_size)
{
    const float* x_pfas = (const float*)d_in[0];
    const float* x_gw   = (const float*)d_in[1];
    const float* x_sw   = (const float*)d_in[2];
    const int* ei_pg_src = (const int*)d_in[3];
    const int* ei_pg_dst = (const int*)d_in[4];
    const int* ei_gp_src = (const int*)d_in[5];
    const int* ei_gp_dst = (const int*)d_in[6];
    const int* ei_ps_src = (const int*)d_in[7];
    const int* ei_ps_dst = (const int*)d_in[8];
    const int* ei_sp_src = (const int*)d_in[9];
    const int* ei_sp_dst = (const int*)d_in[10];
    const float* Wl_pg = (const float*)d_in[11];
    const float* bl_pg = (const float*)d_in[12];
    const float* Wr_pg = (const float*)d_in[13];
    const float* Wl_gp = (const float*)d_in[14];
    const float* bl_gp = (const float*)d_in[15];
    const float* Wr_gp = (const float*)d_in[16];
    const float* Wl_ps = (const float*)d_in[17];
    const float* bl_ps = (const float*)d_in[18];
    const float* Wr_ps = (const float*)d_in[19];
    const float* Wl_sp = (const float*)d_in[20];
    const float* bl_sp = (const float*)d_in[21];
    const float* Wr_sp = (const float*)d_in[22];
    const float* W_gw  = (const float*)d_in[23];
    const float* b_gw  = (const float*)d_in[24];
    const float* W_sw  = (const float*)d_in[25];
    const float* b_sw  = (const float*)d_in[26];

    const int E_PG = in_sizes[3];
    const int E_GP = in_sizes[5];
    const int E_PS = in_sizes[7];
    const int E_SP = in_sizes[9];

    float* out = (float*)d_out;
    float* out_hpf = out;                       // [20000, 128]
    float* out_gw  = out + (size_t)NPF * D;     // [100000]
    float* out_sw  = out_gw + NGW;              // [30000]

    static float *mean_gw = nullptr, *mean_sw = nullptr, *mean_gp = nullptr, *mean_sp = nullptr;
    static float *wr_comb = nullptr;
    static int *cnt = nullptr, *rowptr = nullptr, *cursor = nullptr, *perm = nullptr, *partials = nullptr;
    if (!mean_gw) {
        cudaGetSymbolAddress((void**)&mean_gw, g_mean_gw);
        cudaGetSymbolAddress((void**)&mean_sw, g_mean_sw);
        cudaGetSymbolAddress((void**)&mean_gp, g_mean_gp);
        cudaGetSymbolAddress((void**)&mean_sp, g_mean_sp);
        cudaGetSymbolAddress((void**)&wr_comb, g_wr_comb);
        cudaGetSymbolAddress((void**)&cnt, g_cnt);
        cudaGetSymbolAddress((void**)&rowptr, g_rowptr);
        cudaGetSymbolAddress((void**)&cursor, g_cursor);
        cudaGetSymbolAddress((void**)&perm, g_perm);
        cudaGetSymbolAddress((void**)&partials, g_partials);
    }

    const int off_pg = 0;
    const int off_gp = NGW;
    const int off_ps = NGW + NPF;
    const int off_sp = NGW + NPF + NSW;
    const int poff_pg = 0;
    const int poff_gp = E_PG;
    const int poff_ps = E_PG + E_GP;
    const int poff_sp = E_PG + E_GP + E_PS;

    zero_int_kernel<<<(NTOT / 4 + 255) / 256, 256>>>(cnt, NTOT / 4);
    addw_kernel<<<(D * D + 255) / 256, 256>>>(Wr_gp, Wr_sp, wr_comb);

    struct Rel {
        const int *src, *dst;
        const float* x;
        float* mean;
        int off, poff, N, E;
    };
    Rel rels[4] = {
        {ei_pg_src, ei_pg_dst, x_pfas, mean_gw, off_pg, poff_pg, NGW, E_PG},
        {ei_gp_src, ei_gp_dst, x_gw,   mean_gp, off_gp, poff_gp, NPF, E_GP},
        {ei_ps_src, ei_ps_dst, x_pfas, mean_sw, off_ps, poff_ps, NSW, E_PS},
        {ei_sp_src, ei_sp_dst, x_sw,   mean_sp, off_sp, poff_sp, NPF, E_SP},
    };

    for (int r = 0; r < 4; r++) {
        Rel& q = rels[r];
        hist_kernel<<<(q.E + 255) / 256, 256>>>(q.dst, cnt + q.off, q.E);
    }
    for (int r = 0; r < 4; r++) {
        Rel& q = rels[r];
        int nb = (q.N + 1023) / 1024;
        scan_reduce_kernel<<<nb, 256>>>(cnt + q.off, q.N, partials + r * 128);
        scan_partials_kernel<<<1, 1>>>(partials + r * 128, nb);
        scan_write_kernel<<<nb, 256>>>(cnt + q.off, q.N, partials + r * 128,
                                       rowptr + q.off, cursor + q.off);
    }
    for (int r = 0; r < 4; r++) {
        Rel& q = rels[r];
        permute_kernel<<<(q.E + 255) / 256, 256>>>(q.src, q.dst, cursor + q.off,
                                                   perm + q.poff, q.E);
    }
    for (int r = 0; r < 4; r++) {
        Rel& q = rels[r];
        aggregate_kernel<<<(q.N + 7) / 8, 256>>>(q.x, rowptr + q.off, perm + q.poff,
                                                 q.mean, q.N, q.E);
    }

    // pfas: relu(mean_gp@Wl_gp + mean_sp@Wl_sp + x_pfas@(Wr_gp+Wr_sp) + bl_gp + bl_sp)
    gemm_fused<3, 0><<<(NPF + 127) / 128, 256>>>(
        mean_gp, mean_sp, x_pfas, nullptr,
        Wl_gp, Wl_sp, wr_comb, nullptr,
        bl_gp, bl_sp, nullptr, nullptr,
        out_hpf, NPF);

    // gw head: relu(mean_gw@Wl_pg + x_gw@Wr_pg + bl_pg) @ W_gw + b_gw
    gemm_fused<2, 1><<<(NGW + 127) / 128, 256>>>(
        mean_gw, x_gw, nullptr, nullptr,
        Wl_pg, Wr_pg, nullptr, nullptr,
        bl_pg, nullptr, W_gw, b_gw,
        out_gw, NGW);

    // sw head: relu(mean_sw@Wl_ps + x_sw@Wr_ps + bl_ps) @ W_sw + b_sw
    gemm_fused<2, 1><<<(NSW + 127) / 128, 256>>>(
        mean_sw, x_sw, nullptr, nullptr,
        Wl_ps, Wr_ps, nullptr, nullptr,
        bl_ps, nullptr, W_sw, b_sw,
        out_sw, NSW);

    (void)n_in; (void)out_size;
}